// round 2
// baseline (speedup 1.0000x reference)
#include <cuda_runtime.h>

#define TBS 128

// ---------- packed f32x2 helpers ----------
__device__ __forceinline__ unsigned long long pk2(float a, float b){
    unsigned long long r; asm("mov.b64 %0, {%1,%2};" : "=l"(r) : "f"(a), "f"(b)); return r;
}
__device__ __forceinline__ void upk2(unsigned long long v, float& a, float& b){
    asm("mov.b64 {%0,%1}, %2;" : "=f"(a), "=f"(b) : "l"(v));
}
#define FMA2(d,a,b) asm("fma.rn.f32x2 %0, %1, %2, %0;" : "+l"(d) : "l"(a), "l"(b))

__device__ __forceinline__ float swishf(float x){
    return x / (1.f + __expf(-x));
}

// ---------- shared memory layout (float offsets) ----------
#define S_YTMP 0                        // 51 x TBS   (stage input incl. time slot 50)
#define S_Y    (S_YTMP + 51*TBS)        // 50 x TBS   (base state of current RK step)
#define S_W1   (S_Y + 50*TBS)           // 51 x 52 (padded rows, 16B aligned)
#define S_W2   (S_W1 + 51*52)           // 50 x 52
#define S_B1   (S_W2 + 50*52)           // 50
#define S_B2   (S_B1 + 50)              // 50
#define S_NOW  (S_B2 + 50)              // 800 (node_out_w 50x16)
#define S_NOB  (S_NOW + 800)            // 16
#define S_EN1  (S_NOB + 16)             // 80
#define S_ENB1 (S_EN1 + 80)             // 16
#define S_EN2  (S_ENB1 + 16)            // 256
#define S_ENB2 (S_EN2 + 256)            // 16
#define S_EE1  (S_ENB2 + 16)            // 16
#define S_EEB1 (S_EE1 + 16)             // 16
#define S_EE2  (S_EEB1 + 16)            // 256
#define S_EEB2 (S_EE2 + 256)            // 16
#define S_DW1  (S_EEB2 + 16)            // 256
#define S_DB1  (S_DW1 + 256)            // 16
#define S_DW2  (S_DB1 + 16)             // 256
#define S_DB2  (S_DW2 + 256)            // 16
#define S_DW3  (S_DB2 + 16)             // 16
#define S_DB3  (S_DW3 + 16)             // 1
#define S_TOTAL (S_DB3 + 1)

__device__ __forceinline__ void elatf(float e, const float* ee1, const float* eeb1,
                                      const float* ee2, const float* eeb2, float* out16){
    float a[16];
    #pragma unroll
    for (int j = 0; j < 16; j++) a[j] = swishf(fmaf(e, ee1[j], eeb1[j]));
    #pragma unroll
    for (int j = 0; j < 16; j++){
        float acc = eeb2[j];
        #pragma unroll
        for (int k = 0; k < 16; k++) acc = fmaf(a[k], ee2[k*16 + j], acc);
        out16[j] = acc;
    }
}

__global__ void __launch_bounds__(TBS)
gnode_main_kernel(
    const float* __restrict__ nodes,   const float* __restrict__ edges,
    const float* __restrict__ g,
    const float* __restrict__ enc_n_w1, const float* __restrict__ enc_n_b1,
    const float* __restrict__ enc_n_w2, const float* __restrict__ enc_n_b2,
    const float* __restrict__ enc_e_w1, const float* __restrict__ enc_e_b1,
    const float* __restrict__ enc_e_w2, const float* __restrict__ enc_e_b2,
    const float* __restrict__ ode_w1,   const float* __restrict__ ode_b1,
    const float* __restrict__ ode_w2,   const float* __restrict__ ode_b2,
    const float* __restrict__ node_out_w, const float* __restrict__ node_out_b,
    const float* __restrict__ dec_n_w1, const float* __restrict__ dec_n_b1,
    const float* __restrict__ dec_n_w2, const float* __restrict__ dec_n_b2,
    const float* __restrict__ dec_n_w3, const float* __restrict__ dec_n_b3,
    float* __restrict__ out_nodes, int n)
{
    extern __shared__ float sm[];
    const int tid = threadIdx.x;
    const int e_cnt = n - 1;

    // ---- cooperative weight staging ----
    for (int idx = tid; idx < 51*50; idx += TBS){
        int k = idx / 50; sm[S_W1 + k*52 + (idx - k*50)] = ode_w1[idx];
    }
    for (int idx = tid; idx < 50*50; idx += TBS){
        int k = idx / 50; sm[S_W2 + k*52 + (idx - k*50)] = ode_w2[idx];
    }
    #define CPY(dst, src, cnt) for (int _i = tid; _i < (cnt); _i += TBS) sm[(dst) + _i] = (src)[_i];
    CPY(S_B1,  ode_b1, 50)  CPY(S_B2,  ode_b2, 50)
    CPY(S_NOW, node_out_w, 800) CPY(S_NOB, node_out_b, 16)
    CPY(S_EN1, enc_n_w1, 80) CPY(S_ENB1, enc_n_b1, 16)
    CPY(S_EN2, enc_n_w2, 256) CPY(S_ENB2, enc_n_b2, 16)
    CPY(S_EE1, enc_e_w1, 16) CPY(S_EEB1, enc_e_b1, 16)
    CPY(S_EE2, enc_e_w2, 256) CPY(S_EEB2, enc_e_b2, 16)
    CPY(S_DW1, dec_n_w1, 256) CPY(S_DB1, dec_n_b1, 16)
    CPY(S_DW2, dec_n_w2, 256) CPY(S_DB2, dec_n_b2, 16)
    CPY(S_DW3, dec_n_w3, 16) CPY(S_DB3, dec_n_b3, 1)
    #undef CPY
    __syncthreads();

    const int i = blockIdx.x * TBS + tid;
    if (i >= n) return;

    // ---- node encoder ----
    const float nd0 = nodes[i*5+0], nd1 = nodes[i*5+1], nd2 = nodes[i*5+2];
    const float nd3 = nodes[i*5+3], nd4 = nodes[i*5+4];
    float y0[50];
    {
        float h1[16];
        #pragma unroll
        for (int j = 0; j < 16; j++){
            float a = sm[S_ENB1 + j];
            a = fmaf(nd0, sm[S_EN1 +  0 + j], a);
            a = fmaf(nd1, sm[S_EN1 + 16 + j], a);
            a = fmaf(nd2, sm[S_EN1 + 32 + j], a);
            a = fmaf(nd3, sm[S_EN1 + 48 + j], a);
            a = fmaf(nd4, sm[S_EN1 + 64 + j], a);
            h1[j] = swishf(a);
        }
        #pragma unroll
        for (int j = 0; j < 16; j++){
            float a = sm[S_ENB2 + j];
            #pragma unroll
            for (int k = 0; k < 16; k++) a = fmaf(h1[k], sm[S_EN2 + k*16 + j], a);
            y0[j] = a;
        }
    }
    // ---- edge encoder: sent = elat[i], recv = elat[i-1] (trivial segment structure) ----
    if (i < e_cnt) {
        elatf(edges[i], sm+S_EE1, sm+S_EEB1, sm+S_EE2, sm+S_EEB2, y0+16);
    } else {
        for (int j = 0; j < 16; j++) y0[16+j] = 0.f;
    }
    if (i > 0) {
        elatf(edges[i-1], sm+S_EE1, sm+S_EEB1, sm+S_EE2, sm+S_EEB2, y0+32);
    } else {
        for (int j = 0; j < 16; j++) y0[32+j] = 0.f;
    }
    y0[48] = g[0]; y0[49] = g[1];

    // state into shared (per-thread columns) + packed accumulator
    unsigned long long ynew[25];
    #pragma unroll
    for (int j2 = 0; j2 < 25; j2++){
        sm[S_Y    + (2*j2)*TBS + tid] = y0[2*j2];
        sm[S_Y    + (2*j2+1)*TBS + tid] = y0[2*j2+1];
        sm[S_YTMP + (2*j2)*TBS + tid] = y0[2*j2];
        sm[S_YTMP + (2*j2+1)*TBS + tid] = y0[2*j2+1];
        ynew[j2] = pk2(y0[2*j2], y0[2*j2+1]);
    }

    // ---- RK4 ODE: 4 steps x 4 stages ----
    const float h = 0.25f;
    float t = 0.f;
    #pragma unroll 1
    for (int step = 0; step < 4; step++){
        float tin = t;
        #pragma unroll 1
        for (int st = 0; st < 4; st++){
            sm[S_YTMP + 50*TBS + tid] = tin;   // time slot
            unsigned long long acc[25];
            // ---- matmul1: relu(inp @ W1 + b1) ----
            #pragma unroll
            for (int j2 = 0; j2 < 25; j2++)
                acc[j2] = ((const unsigned long long*)(sm + S_B1))[j2];
            #pragma unroll 3
            for (int k = 0; k < 51; k++){
                float yk = sm[S_YTMP + k*TBS + tid];
                unsigned long long ykk = pk2(yk, yk);
                const float* wr = sm + S_W1 + k*52;
                const ulonglong2* wv = (const ulonglong2*)wr;
                #pragma unroll
                for (int q = 0; q < 12; q++){
                    ulonglong2 w = wv[q];
                    FMA2(acc[2*q],   ykk, w.x);
                    FMA2(acc[2*q+1], ykk, w.y);
                }
                FMA2(acc[24], ykk, ((const unsigned long long*)wr)[24]);
            }
            // relu -> z (stored back into YTMP columns)
            #pragma unroll
            for (int j2 = 0; j2 < 25; j2++){
                float a, b; upk2(acc[j2], a, b);
                sm[S_YTMP + (2*j2)*TBS + tid]   = fmaxf(a, 0.f);
                sm[S_YTMP + (2*j2+1)*TBS + tid] = fmaxf(b, 0.f);
            }
            // ---- matmul2: z @ W2 + b2 -> k ----
            #pragma unroll
            for (int j2 = 0; j2 < 25; j2++)
                acc[j2] = ((const unsigned long long*)(sm + S_B2))[j2];
            #pragma unroll 2
            for (int k = 0; k < 50; k++){
                float zk = sm[S_YTMP + k*TBS + tid];
                unsigned long long zkk = pk2(zk, zk);
                const float* wr = sm + S_W2 + k*52;
                const ulonglong2* wv = (const ulonglong2*)wr;
                #pragma unroll
                for (int q = 0; q < 12; q++){
                    ulonglong2 w = wv[q];
                    FMA2(acc[2*q],   zkk, w.x);
                    FMA2(acc[2*q+1], zkk, w.y);
                }
                FMA2(acc[24], zkk, ((const unsigned long long*)wr)[24]);
            }
            // ynew += w_s * k
            float wc = (st == 0 || st == 3) ? h*(1.f/6.f) : h*(1.f/3.f);
            unsigned long long wp = pk2(wc, wc);
            #pragma unroll
            for (int j2 = 0; j2 < 25; j2++) FMA2(ynew[j2], wp, acc[j2]);
            // rebuild stage input: ytmp = y + a_s * k
            if (st < 3){
                float ain = (st == 2) ? h : 0.5f*h;
                tin = (st == 2) ? (t + h) : (t + 0.5f*h);
                #pragma unroll
                for (int j2 = 0; j2 < 25; j2++){
                    float ka, kb; upk2(acc[j2], ka, kb);
                    float ya = sm[S_Y + (2*j2)*TBS + tid];
                    float yb = sm[S_Y + (2*j2+1)*TBS + tid];
                    sm[S_YTMP + (2*j2)*TBS + tid]   = fmaf(ain, ka, ya);
                    sm[S_YTMP + (2*j2+1)*TBS + tid] = fmaf(ain, kb, yb);
                }
            }
        }
        // commit step: y = ytmp = ynew
        #pragma unroll
        for (int j2 = 0; j2 < 25; j2++){
            float a, b; upk2(ynew[j2], a, b);
            sm[S_Y    + (2*j2)*TBS + tid] = a;
            sm[S_Y    + (2*j2+1)*TBS + tid] = b;
            sm[S_YTMP + (2*j2)*TBS + tid] = a;
            sm[S_YTMP + (2*j2+1)*TBS + tid] = b;
        }
        t += h;
    }

    // ---- decoder ----
    float yT[50];
    #pragma unroll
    for (int j2 = 0; j2 < 25; j2++) upk2(ynew[j2], yT[2*j2], yT[2*j2+1]);

    float nl2[16];
    #pragma unroll
    for (int j = 0; j < 16; j++){
        float a = sm[S_NOB + j];
        #pragma unroll
        for (int k = 0; k < 50; k++) a = fmaf(yT[k], sm[S_NOW + k*16 + j], a);
        nl2[j] = a;
    }
    float d1[16];
    #pragma unroll
    for (int j = 0; j < 16; j++){
        float a = sm[S_DB1 + j];
        #pragma unroll
        for (int k = 0; k < 16; k++) a = fmaf(nl2[k], sm[S_DW1 + k*16 + j], a);
        d1[j] = swishf(a);
    }
    float d2[16];
    #pragma unroll
    for (int j = 0; j < 16; j++){
        float a = sm[S_DB2 + j];
        #pragma unroll
        for (int k = 0; k < 16; k++) a = fmaf(d1[k], sm[S_DW2 + k*16 + j], a);
        d2[j] = swishf(a);
    }
    float acc_p = sm[S_DB3];
    #pragma unroll
    for (int k = 0; k < 16; k++) acc_p = fmaf(d2[k], sm[S_DW3 + k], acc_p);

    const float vel = fmaf(acc_p, 0.01f, nd4);
    const float pos = fmaf(vel,   0.01f, nd0);

    out_nodes[i*6 + 0] = pos;
    out_nodes[i*6 + 1] = nd2;
    out_nodes[i*6 + 2] = nd3;
    out_nodes[i*6 + 3] = nd4;
    out_nodes[i*6 + 4] = vel;
    out_nodes[i*6 + 5] = acc_p;
}

__global__ void gnode_edge_kernel(const float* __restrict__ out_nodes,
                                  float* __restrict__ out_edges,
                                  const float* __restrict__ g,
                                  float* __restrict__ out_g, int e_cnt)
{
    int e = blockIdx.x * blockDim.x + threadIdx.x;
    if (e < e_cnt) out_edges[e] = out_nodes[(e+1)*6] - out_nodes[e*6];
    if (e == 0){ out_g[0] = g[0] + 1.f; out_g[1] = g[1]; }
}

extern "C" void kernel_launch(void* const* d_in, const int* in_sizes, int n_in,
                              void* d_out, int out_size)
{
    const float* nodes      = (const float*)d_in[0];
    const float* edges      = (const float*)d_in[1];
    const float* g          = (const float*)d_in[2];
    const float* enc_n_w1   = (const float*)d_in[3];
    const float* enc_n_b1   = (const float*)d_in[4];
    const float* enc_n_w2   = (const float*)d_in[5];
    const float* enc_n_b2   = (const float*)d_in[6];
    const float* enc_e_w1   = (const float*)d_in[7];
    const float* enc_e_b1   = (const float*)d_in[8];
    const float* enc_e_w2   = (const float*)d_in[9];
    const float* enc_e_b2   = (const float*)d_in[10];
    const float* ode_w1     = (const float*)d_in[11];
    const float* ode_b1     = (const float*)d_in[12];
    const float* ode_w2     = (const float*)d_in[13];
    const float* ode_b2     = (const float*)d_in[14];
    const float* node_out_w = (const float*)d_in[15];
    const float* node_out_b = (const float*)d_in[16];
    const float* dec_n_w1   = (const float*)d_in[17];
    const float* dec_n_b1   = (const float*)d_in[18];
    const float* dec_n_w2   = (const float*)d_in[19];
    const float* dec_n_b2   = (const float*)d_in[20];
    const float* dec_n_w3   = (const float*)d_in[21];
    const float* dec_n_b3   = (const float*)d_in[22];

    const int n = in_sizes[0] / 5;     // N nodes
    const int e_cnt = n - 1;
    float* out = (float*)d_out;
    float* out_edges = out + (size_t)n * 6;
    float* out_g = out_edges + e_cnt;

    const size_t smem_bytes = (size_t)S_TOTAL * sizeof(float);
    cudaFuncSetAttribute(gnode_main_kernel,
                         cudaFuncAttributeMaxDynamicSharedMemorySize, (int)smem_bytes);

    gnode_main_kernel<<<(n + TBS - 1) / TBS, TBS, smem_bytes>>>(
        nodes, edges, g,
        enc_n_w1, enc_n_b1, enc_n_w2, enc_n_b2,
        enc_e_w1, enc_e_b1, enc_e_w2, enc_e_b2,
        ode_w1, ode_b1, ode_w2, ode_b2,
        node_out_w, node_out_b,
        dec_n_w1, dec_n_b1, dec_n_w2, dec_n_b2, dec_n_w3, dec_n_b3,
        out, n);

    gnode_edge_kernel<<<(e_cnt + 255) / 256, 256>>>(out, out_edges, g, out_g, e_cnt);
}

// round 5
// speedup vs baseline: 5.7151x; 5.7151x over previous
#include <cuda_runtime.h>
#include <cuda_bf16.h>
#include <cstdint>

#define TBS 256
#define NPB 128        // nodes per block (8 warps x 16 rows)
#define WSTRIDE 72     // bf16 elements per weight row (padded: conflict-free B-frag loads)

// ---- dynamic smem byte offsets ----
#define OFF_W1 0
#define OFF_W2 (OFF_W1 + 64*WSTRIDE*2)          // 9216
#define OFF_F  (OFF_W2 + 64*WSTRIDE*2)          // 18432
#define F_CNT 2049
#define OFF_STAGE ((OFF_F + F_CNT*4 + 15) & ~15)
#define STG_STRIDE 56
#define DYN_BYTES (OFF_STAGE + NPB*STG_STRIDE*4)

// float-index offsets within F
#define FEN1 0
#define FENB1 80
#define FEN2 96
#define FENB2 352
#define FEE1 368
#define FEEB1 384
#define FEE2 400
#define FEEB2 656
#define FNOW 672
#define FNOB 1472
#define FDW1 1488
#define FDB1 1744
#define FDW2 1760
#define FDB2 2016
#define FDW3 2032
#define FDB3 2048

__device__ __forceinline__ float swishf(float x){ return x / (1.f + __expf(-x)); }

// pack two fp32 -> bf16x2, lo in low 16 bits
__device__ __forceinline__ uint32_t f2bf2(float lo, float hi){
    uint32_t r; asm("cvt.rn.bf16x2.f32 %0, %1, %2;" : "=r"(r) : "f"(hi), "f"(lo)); return r;
}

__device__ __forceinline__ void mma16816(float d[4], const uint32_t a[4], const uint32_t b[2]){
    asm volatile("mma.sync.aligned.m16n8k16.row.col.f32.bf16.bf16.f32 "
        "{%0,%1,%2,%3}, {%4,%5,%6,%7}, {%8,%9}, {%0,%1,%2,%3};"
        : "+f"(d[0]),"+f"(d[1]),"+f"(d[2]),"+f"(d[3])
        : "r"(a[0]),"r"(a[1]),"r"(a[2]),"r"(a[3]), "r"(b[0]),"r"(b[1]));
}

__device__ __forceinline__ void elatf(float e, const float* F, float* out16){
    float a[16];
    #pragma unroll
    for (int j = 0; j < 16; j++) a[j] = swishf(fmaf(e, F[FEE1+j], F[FEEB1+j]));
    #pragma unroll
    for (int j = 0; j < 16; j++){
        float acc = F[FEEB2+j];
        #pragma unroll
        for (int k = 0; k < 16; k++) acc = fmaf(a[k], F[FEE2 + k*16 + j], acc);
        out16[j] = acc;
    }
}

__global__ void __launch_bounds__(TBS)
gnode_main_kernel(
    const float* __restrict__ nodes,   const float* __restrict__ edges,
    const float* __restrict__ g,
    const float* __restrict__ enc_n_w1, const float* __restrict__ enc_n_b1,
    const float* __restrict__ enc_n_w2, const float* __restrict__ enc_n_b2,
    const float* __restrict__ enc_e_w1, const float* __restrict__ enc_e_b1,
    const float* __restrict__ enc_e_w2, const float* __restrict__ enc_e_b2,
    const float* __restrict__ ode_w1,   const float* __restrict__ ode_b1,
    const float* __restrict__ ode_w2,   const float* __restrict__ ode_b2,
    const float* __restrict__ node_out_w, const float* __restrict__ node_out_b,
    const float* __restrict__ dec_n_w1, const float* __restrict__ dec_n_b1,
    const float* __restrict__ dec_n_w2, const float* __restrict__ dec_n_b2,
    const float* __restrict__ dec_n_w3, const float* __restrict__ dec_n_b3,
    float* __restrict__ out_nodes, int n)
{
    extern __shared__ char dyn[];
    const int tid = threadIdx.x;
    float* F = (float*)(dyn + OFF_F);
    float* stg = (float*)(dyn + OFF_STAGE);
    __nv_bfloat16* W1s = (__nv_bfloat16*)(dyn + OFF_W1);
    __nv_bfloat16* W2s = (__nv_bfloat16*)(dyn + OFF_W2);

    // ---- stage ODE weights (transposed, bias/time rows folded, zero padded) ----
    for (int idx = tid; idx < 64*WSTRIDE; idx += TBS){
        int nrow = idx / WSTRIDE, k = idx - nrow*WSTRIDE;
        float v1 = 0.f, v2 = 0.f;
        if (nrow < 50){
            if (k < 51) v1 = ode_w1[k*50 + nrow];        // rows 0..49 = y, row 50 = t
            else if (k == 51) v1 = ode_b1[nrow];          // bias row
            if (k < 50) v2 = ode_w2[k*50 + nrow];
            else if (k == 50) v2 = ode_b2[nrow];          // bias row
        }
        W1s[idx] = __float2bfloat16(v1);
        W2s[idx] = __float2bfloat16(v2);
    }
    // ---- stage fp32 enc/dec tables ----
    #define CPY(dst, src, cnt) for (int _i = tid; _i < (cnt); _i += TBS) F[(dst) + _i] = (src)[_i];
    CPY(FEN1, enc_n_w1, 80) CPY(FENB1, enc_n_b1, 16)
    CPY(FEN2, enc_n_w2, 256) CPY(FENB2, enc_n_b2, 16)
    CPY(FEE1, enc_e_w1, 16) CPY(FEEB1, enc_e_b1, 16)
    CPY(FEE2, enc_e_w2, 256) CPY(FEEB2, enc_e_b2, 16)
    CPY(FNOW, node_out_w, 800) CPY(FNOB, node_out_b, 16)
    CPY(FDW1, dec_n_w1, 256) CPY(FDB1, dec_n_b1, 16)
    CPY(FDW2, dec_n_w2, 256) CPY(FDB2, dec_n_b2, 16)
    CPY(FDW3, dec_n_w3, 16) CPY(FDB3, dec_n_b3, 1)
    #undef CPY
    __syncthreads();

    const int e_cnt = n - 1;
    const int i = blockIdx.x * NPB + tid;       // node for encode/decode phases (tid < NPB)
    const bool owns_node = (tid < NPB);
    const bool valid = owns_node && (i < n);

    // ---- encoder (fp32 exact), write y0 into stage ----
    float nd0 = 0.f, nd2 = 0.f, nd3 = 0.f, nd4 = 0.f;
    if (owns_node){
        float y0[50];
        #pragma unroll
        for (int j = 0; j < 50; j++) y0[j] = 0.f;
        if (valid){
            nd0 = nodes[i*5+0];
            float nd1 = nodes[i*5+1];
            nd2 = nodes[i*5+2]; nd3 = nodes[i*5+3]; nd4 = nodes[i*5+4];
            float h1[16];
            #pragma unroll
            for (int j = 0; j < 16; j++){
                float a = F[FENB1+j];
                a = fmaf(nd0, F[FEN1 +  0 + j], a);
                a = fmaf(nd1, F[FEN1 + 16 + j], a);
                a = fmaf(nd2, F[FEN1 + 32 + j], a);
                a = fmaf(nd3, F[FEN1 + 48 + j], a);
                a = fmaf(nd4, F[FEN1 + 64 + j], a);
                h1[j] = swishf(a);
            }
            #pragma unroll
            for (int j = 0; j < 16; j++){
                float a = F[FENB2+j];
                #pragma unroll
                for (int k = 0; k < 16; k++) a = fmaf(h1[k], F[FEN2 + k*16 + j], a);
                y0[j] = a;
            }
            if (i < e_cnt) elatf(edges[i],   F, y0+16);
            if (i > 0)     elatf(edges[i-1], F, y0+32);
            y0[48] = g[0]; y0[49] = g[1];
        }
        float* sr = stg + tid*STG_STRIDE;
        #pragma unroll
        for (int c = 0; c < 50; c++) sr[c] = y0[c];
        #pragma unroll
        for (int c = 50; c < STG_STRIDE; c++) sr[c] = 0.f;
    }
    __syncthreads();

    // ---- load initial state fragments ----
    const int lane = tid & 31, w = tid >> 5;
    const int gq = lane >> 2, tq = lane & 3;
    float y[7][4], yn[7][4], x[7][4];
    {
        const float* s0 = stg + (w*16 + gq)*STG_STRIDE + 2*tq;
        const float* s1 = s0 + 8*STG_STRIDE;
        #pragma unroll
        for (int j = 0; j < 7; j++){
            y[j][0] = s0[8*j];   y[j][1] = s0[8*j + 1];
            y[j][2] = s1[8*j];   y[j][3] = s1[8*j + 1];
            #pragma unroll
            for (int q = 0; q < 4; q++){ yn[j][q] = y[j][q]; x[j][q] = y[j][q]; }
        }
    }

    // ---- RK4 ODE: state stays in fragments ----
    const float h = 0.25f;
    float tcur = 0.f;
    #pragma unroll 1
    for (int step = 0; step < 4; step++){
        #pragma unroll 1
        for (int st = 0; st < 4; st++){
            const float tval = tcur + ((st == 0) ? 0.f : ((st == 3) ? h : 0.5f*h));

            // A1 fragments from x (cols 0..49 state, 50=t, 51=1, 52..63=0)
            uint32_t A[4][4];
            #pragma unroll
            for (int kk = 0; kk < 3; kk++){
                A[kk][0] = f2bf2(x[2*kk][0],   x[2*kk][1]);
                A[kk][1] = f2bf2(x[2*kk][2],   x[2*kk][3]);
                A[kk][2] = f2bf2(x[2*kk+1][0], x[2*kk+1][1]);
                A[kk][3] = f2bf2(x[2*kk+1][2], x[2*kk+1][3]);
            }
            {
                float a0 = x[6][0], a1 = x[6][1], a2 = x[6][2], a3 = x[6][3];
                if (tq == 1){ a0 = tval; a1 = 1.f; a2 = tval; a3 = 1.f; }
                A[3][0] = f2bf2(a0, a1); A[3][1] = f2bf2(a2, a3);
                A[3][2] = 0u; A[3][3] = 0u;
            }

            // MMA1: d = relu(inp @ W1 + b1)
            float d[7][4];
            #pragma unroll
            for (int j = 0; j < 7; j++){
                d[j][0] = d[j][1] = d[j][2] = d[j][3] = 0.f;
                const __nv_bfloat16* bp = W1s + (8*j + gq)*WSTRIDE + 2*tq;
                #pragma unroll
                for (int kk = 0; kk < 4; kk++){
                    uint32_t b[2];
                    b[0] = *(const uint32_t*)(bp + 16*kk);
                    b[1] = *(const uint32_t*)(bp + 16*kk + 8);
                    mma16816(d[j], A[kk], b);
                }
            }
            #pragma unroll
            for (int j = 0; j < 7; j++){
                #pragma unroll
                for (int q = 0; q < 4; q++) d[j][q] = fmaxf(d[j][q], 0.f);
            }
            if (tq == 1){ d[6][0] = 1.f; d[6][2] = 1.f; }   // bias col 50 for MMA2

            // A2 fragments from d
            uint32_t A2r[4][4];
            #pragma unroll
            for (int kk = 0; kk < 3; kk++){
                A2r[kk][0] = f2bf2(d[2*kk][0],   d[2*kk][1]);
                A2r[kk][1] = f2bf2(d[2*kk][2],   d[2*kk][3]);
                A2r[kk][2] = f2bf2(d[2*kk+1][0], d[2*kk+1][1]);
                A2r[kk][3] = f2bf2(d[2*kk+1][2], d[2*kk+1][3]);
            }
            A2r[3][0] = f2bf2(d[6][0], d[6][1]);
            A2r[3][1] = f2bf2(d[6][2], d[6][3]);
            A2r[3][2] = 0u; A2r[3][3] = 0u;

            // MMA2: kv = z @ W2 + b2
            float kv[7][4];
            #pragma unroll
            for (int j = 0; j < 7; j++){
                kv[j][0] = kv[j][1] = kv[j][2] = kv[j][3] = 0.f;
                const __nv_bfloat16* bp = W2s + (8*j + gq)*WSTRIDE + 2*tq;
                #pragma unroll
                for (int kk = 0; kk < 4; kk++){
                    uint32_t b[2];
                    b[0] = *(const uint32_t*)(bp + 16*kk);
                    b[1] = *(const uint32_t*)(bp + 16*kk + 8);
                    mma16816(kv[j], A2r[kk], b);
                }
            }

            // RK4 combine (fp32)
            const float wc = (st == 0 || st == 3) ? h*(1.f/6.f) : h*(1.f/3.f);
            #pragma unroll
            for (int j = 0; j < 7; j++){
                #pragma unroll
                for (int q = 0; q < 4; q++) yn[j][q] = fmaf(wc, kv[j][q], yn[j][q]);
            }
            if (st < 3){
                const float ain = (st == 2) ? h : 0.5f*h;
                #pragma unroll
                for (int j = 0; j < 7; j++){
                    #pragma unroll
                    for (int q = 0; q < 4; q++) x[j][q] = fmaf(ain, kv[j][q], y[j][q]);
                }
            } else {
                #pragma unroll
                for (int j = 0; j < 7; j++){
                    #pragma unroll
                    for (int q = 0; q < 4; q++){ y[j][q] = yn[j][q]; x[j][q] = yn[j][q]; }
                }
                tcur += h;
            }
        }
    }

    // ---- write final state fragments back to stage ----
    {
        float* s0 = stg + (w*16 + gq)*STG_STRIDE + 2*tq;
        float* s1 = s0 + 8*STG_STRIDE;
        #pragma unroll
        for (int j = 0; j < 7; j++){
            s0[8*j] = yn[j][0];  s0[8*j + 1] = yn[j][1];
            s1[8*j] = yn[j][2];  s1[8*j + 1] = yn[j][3];
        }
    }
    __syncthreads();

    // ---- decoder (fp32 exact) ----
    if (valid){
        const float* sr = stg + tid*STG_STRIDE;
        float yT[50];
        #pragma unroll
        for (int k = 0; k < 50; k++) yT[k] = sr[k];

        float nl2[16];
        #pragma unroll
        for (int j = 0; j < 16; j++){
            float a = F[FNOB+j];
            #pragma unroll
            for (int k = 0; k < 50; k++) a = fmaf(yT[k], F[FNOW + k*16 + j], a);
            nl2[j] = a;
        }
        float d1[16];
        #pragma unroll
        for (int j = 0; j < 16; j++){
            float a = F[FDB1+j];
            #pragma unroll
            for (int k = 0; k < 16; k++) a = fmaf(nl2[k], F[FDW1 + k*16 + j], a);
            d1[j] = swishf(a);
        }
        float d2[16];
        #pragma unroll
        for (int j = 0; j < 16; j++){
            float a = F[FDB2+j];
            #pragma unroll
            for (int k = 0; k < 16; k++) a = fmaf(d1[k], F[FDW2 + k*16 + j], a);
            d2[j] = swishf(a);
        }
        float acc_p = F[FDB3];
        #pragma unroll
        for (int k = 0; k < 16; k++) acc_p = fmaf(d2[k], F[FDW3 + k], acc_p);

        const float vel = fmaf(acc_p, 0.01f, nd4);
        const float pos = fmaf(vel,   0.01f, nd0);
        out_nodes[i*6 + 0] = pos;
        out_nodes[i*6 + 1] = nd2;
        out_nodes[i*6 + 2] = nd3;
        out_nodes[i*6 + 3] = nd4;
        out_nodes[i*6 + 4] = vel;
        out_nodes[i*6 + 5] = acc_p;
    }
}

__global__ void gnode_edge_kernel(const float* __restrict__ out_nodes,
                                  float* __restrict__ out_edges,
                                  const float* __restrict__ g,
                                  float* __restrict__ out_g, int e_cnt)
{
    int e = blockIdx.x * blockDim.x + threadIdx.x;
    if (e < e_cnt) out_edges[e] = out_nodes[(e+1)*6] - out_nodes[e*6];
    if (e == 0){ out_g[0] = g[0] + 1.f; out_g[1] = g[1]; }
}

extern "C" void kernel_launch(void* const* d_in, const int* in_sizes, int n_in,
                              void* d_out, int out_size)
{
    const float* nodes      = (const float*)d_in[0];
    const float* edges      = (const float*)d_in[1];
    const float* g          = (const float*)d_in[2];
    const float* enc_n_w1   = (const float*)d_in[3];
    const float* enc_n_b1   = (const float*)d_in[4];
    const float* enc_n_w2   = (const float*)d_in[5];
    const float* enc_n_b2   = (const float*)d_in[6];
    const float* enc_e_w1   = (const float*)d_in[7];
    const float* enc_e_b1   = (const float*)d_in[8];
    const float* enc_e_w2   = (const float*)d_in[9];
    const float* enc_e_b2   = (const float*)d_in[10];
    const float* ode_w1     = (const float*)d_in[11];
    const float* ode_b1     = (const float*)d_in[12];
    const float* ode_w2     = (const float*)d_in[13];
    const float* ode_b2     = (const float*)d_in[14];
    const float* node_out_w = (const float*)d_in[15];
    const float* node_out_b = (const float*)d_in[16];
    const float* dec_n_w1   = (const float*)d_in[17];
    const float* dec_n_b1   = (const float*)d_in[18];
    const float* dec_n_w2   = (const float*)d_in[19];
    const float* dec_n_b2   = (const float*)d_in[20];
    const float* dec_n_w3   = (const float*)d_in[21];
    const float* dec_n_b3   = (const float*)d_in[22];

    const int n = in_sizes[0] / 5;
    const int e_cnt = n - 1;
    float* out = (float*)d_out;
    float* out_edges = out + (size_t)n * 6;
    float* out_g = out_edges + e_cnt;

    cudaFuncSetAttribute(gnode_main_kernel,
                         cudaFuncAttributeMaxDynamicSharedMemorySize, DYN_BYTES);

    gnode_main_kernel<<<(n + NPB - 1) / NPB, TBS, DYN_BYTES>>>(
        nodes, edges, g,
        enc_n_w1, enc_n_b1, enc_n_w2, enc_n_b2,
        enc_e_w1, enc_e_b1, enc_e_w2, enc_e_b2,
        ode_w1, ode_b1, ode_w2, ode_b2,
        node_out_w, node_out_b,
        dec_n_w1, dec_n_b1, dec_n_w2, dec_n_b2, dec_n_w3, dec_n_b3,
        out, n);

    gnode_edge_kernel<<<(e_cnt + 255) / 256, 256>>>(out, out_edges, g, out_g, e_cnt);
}

// round 8
// speedup vs baseline: 5.9093x; 1.0340x over previous
#include <cuda_runtime.h>
#include <cuda_bf16.h>
#include <cstdint>

#define TBS 256
#define NPB 128        // nodes per block (8 warps x 16 rows)
#define WSTRIDE 72     // bf16 elements per weight row (rows hit distinct banks for LDSM)

// ---- dynamic smem byte offsets ----
#define OFF_W1 0
#define OFF_W2 (OFF_W1 + 64*WSTRIDE*2)          // 9216
#define OFF_F  (OFF_W2 + 64*WSTRIDE*2)          // 18432
#define F_CNT 2049
#define OFF_STAGE ((OFF_F + F_CNT*4 + 15) & ~15)
#define STG_STRIDE 57
#define DYN_BYTES (OFF_STAGE + NPB*STG_STRIDE*4)

// float-index offsets within F
#define FEN1 0
#define FENB1 80
#define FEN2 96
#define FENB2 352
#define FEE1 368
#define FEEB1 384
#define FEE2 400
#define FEEB2 656
#define FNOW 672
#define FNOB 1472
#define FDW1 1488
#define FDB1 1744
#define FDW2 1760
#define FDB2 2016
#define FDW3 2032
#define FDB3 2048

// compact positions for the edge kernel (static device scratch — allowed)
__device__ float g_pos_buf[262144];

__device__ __forceinline__ float swishf(float x){ return x / (1.f + __expf(-x)); }

__device__ __forceinline__ uint32_t smem_u32(const void* p){
    uint32_t a; asm("{ .reg .u64 t; cvta.to.shared.u64 t, %1; cvt.u32.u64 %0, t; }" : "=r"(a) : "l"(p)); return a;
}

// pack two fp32 -> bf16x2, lo in low 16 bits
__device__ __forceinline__ uint32_t f2bf2(float lo, float hi){
    uint32_t r; asm("cvt.rn.bf16x2.f32 %0, %1, %2;" : "=r"(r) : "f"(hi), "f"(lo)); return r;
}

__device__ __forceinline__ void mma16816(float d[4], const uint32_t a[4], uint32_t b0, uint32_t b1){
    asm volatile("mma.sync.aligned.m16n8k16.row.col.f32.bf16.bf16.f32 "
        "{%0,%1,%2,%3}, {%4,%5,%6,%7}, {%8,%9}, {%0,%1,%2,%3};"
        : "+f"(d[0]),"+f"(d[1]),"+f"(d[2]),"+f"(d[3])
        : "r"(a[0]),"r"(a[1]),"r"(a[2]),"r"(a[3]), "r"(b0),"r"(b1));
}

#define LDSM_X4(r0,r1,r2,r3,addr) \
    asm volatile("ldmatrix.sync.aligned.m8n8.x4.shared.b16 {%0,%1,%2,%3}, [%4];" \
        : "=r"(r0),"=r"(r1),"=r"(r2),"=r"(r3) : "r"(addr))

__device__ __forceinline__ void elatf(float e, const float* F, float* out16){
    float a[16];
    #pragma unroll
    for (int j = 0; j < 16; j++) a[j] = swishf(fmaf(e, F[FEE1+j], F[FEEB1+j]));
    #pragma unroll
    for (int j = 0; j < 16; j++){
        float acc = F[FEEB2+j];
        #pragma unroll
        for (int k = 0; k < 16; k++) acc = fmaf(a[k], F[FEE2 + k*16 + j], acc);
        out16[j] = acc;
    }
}

__global__ void __launch_bounds__(TBS)
gnode_main_kernel(
    const float* __restrict__ nodes,   const float* __restrict__ edges,
    const float* __restrict__ g,
    const float* __restrict__ enc_n_w1, const float* __restrict__ enc_n_b1,
    const float* __restrict__ enc_n_w2, const float* __restrict__ enc_n_b2,
    const float* __restrict__ enc_e_w1, const float* __restrict__ enc_e_b1,
    const float* __restrict__ enc_e_w2, const float* __restrict__ enc_e_b2,
    const float* __restrict__ ode_w1,   const float* __restrict__ ode_b1,
    const float* __restrict__ ode_w2,   const float* __restrict__ ode_b2,
    const float* __restrict__ node_out_w, const float* __restrict__ node_out_b,
    const float* __restrict__ dec_n_w1, const float* __restrict__ dec_n_b1,
    const float* __restrict__ dec_n_w2, const float* __restrict__ dec_n_b2,
    const float* __restrict__ dec_n_w3, const float* __restrict__ dec_n_b3,
    float* __restrict__ out_nodes, int n)
{
    extern __shared__ char dyn[];
    const int tid = threadIdx.x;
    float* F = (float*)(dyn + OFF_F);
    float* stg = (float*)(dyn + OFF_STAGE);
    __nv_bfloat16* W1s = (__nv_bfloat16*)(dyn + OFF_W1);
    __nv_bfloat16* W2s = (__nv_bfloat16*)(dyn + OFF_W2);

    // ---- stage ODE weights (transposed, bias/time rows folded, zero padded) ----
    for (int idx = tid; idx < 64*WSTRIDE; idx += TBS){
        int nrow = idx / WSTRIDE, k = idx - nrow*WSTRIDE;
        float v1 = 0.f, v2 = 0.f;
        if (nrow < 50){
            if (k < 51) v1 = ode_w1[k*50 + nrow];        // cols 0..49 = y, col 50 = t
            else if (k == 51) v1 = ode_b1[nrow];          // bias col
            if (k < 50) v2 = ode_w2[k*50 + nrow];
            else if (k == 50) v2 = ode_b2[nrow];          // bias col
        }
        W1s[idx] = __float2bfloat16(v1);
        W2s[idx] = __float2bfloat16(v2);
    }
    // ---- stage fp32 enc/dec tables ----
    #define CPY(dst, src, cnt) for (int _i = tid; _i < (cnt); _i += TBS) F[(dst) + _i] = (src)[_i];
    CPY(FEN1, enc_n_w1, 80) CPY(FENB1, enc_n_b1, 16)
    CPY(FEN2, enc_n_w2, 256) CPY(FENB2, enc_n_b2, 16)
    CPY(FEE1, enc_e_w1, 16) CPY(FEEB1, enc_e_b1, 16)
    CPY(FEE2, enc_e_w2, 256) CPY(FEEB2, enc_e_b2, 16)
    CPY(FNOW, node_out_w, 800) CPY(FNOB, node_out_b, 16)
    CPY(FDW1, dec_n_w1, 256) CPY(FDB1, dec_n_b1, 16)
    CPY(FDW2, dec_n_w2, 256) CPY(FDB2, dec_n_b2, 16)
    CPY(FDW3, dec_n_w3, 16) CPY(FDB3, dec_n_b3, 1)
    #undef CPY
    __syncthreads();

    const int e_cnt = n - 1;
    const int i = blockIdx.x * NPB + tid;       // node for encode/decode phases (tid < NPB)
    const bool owns_node = (tid < NPB);
    const bool valid = owns_node && (i < n);

    // ---- encoder (fp32 exact), write y0 into stage ----
    float nd0 = 0.f, nd2 = 0.f, nd3 = 0.f, nd4 = 0.f;
    if (owns_node){
        float y0[50];
        #pragma unroll
        for (int j = 0; j < 50; j++) y0[j] = 0.f;
        if (valid){
            nd0 = nodes[i*5+0];
            float nd1 = nodes[i*5+1];
            nd2 = nodes[i*5+2]; nd3 = nodes[i*5+3]; nd4 = nodes[i*5+4];
            float h1[16];
            #pragma unroll
            for (int j = 0; j < 16; j++){
                float a = F[FENB1+j];
                a = fmaf(nd0, F[FEN1 +  0 + j], a);
                a = fmaf(nd1, F[FEN1 + 16 + j], a);
                a = fmaf(nd2, F[FEN1 + 32 + j], a);
                a = fmaf(nd3, F[FEN1 + 48 + j], a);
                a = fmaf(nd4, F[FEN1 + 64 + j], a);
                h1[j] = swishf(a);
            }
            #pragma unroll
            for (int j = 0; j < 16; j++){
                float a = F[FENB2+j];
                #pragma unroll
                for (int k = 0; k < 16; k++) a = fmaf(h1[k], F[FEN2 + k*16 + j], a);
                y0[j] = a;
            }
            if (i < e_cnt) elatf(edges[i],   F, y0+16);
            if (i > 0)     elatf(edges[i-1], F, y0+32);
            y0[48] = g[0]; y0[49] = g[1];
        }
        float* sr = stg + tid*STG_STRIDE;
        #pragma unroll
        for (int c = 0; c < 50; c++) sr[c] = y0[c];
        #pragma unroll
        for (int c = 50; c < STG_STRIDE; c++) sr[c] = 0.f;
    }
    __syncthreads();

    // ---- load initial state fragments ----
    const int lane = tid & 31, w = tid >> 5;
    const int gq = lane >> 2, tq = lane & 3;
    float y[7][4], yn[7][4], x[7][4];
    {
        const float* s0 = stg + (w*16 + gq)*STG_STRIDE + 2*tq;
        const float* s1 = s0 + 8*STG_STRIDE;
        #pragma unroll
        for (int j = 0; j < 7; j++){
            y[j][0] = s0[8*j];   y[j][1] = s0[8*j + 1];
            y[j][2] = s1[8*j];   y[j][3] = s1[8*j + 1];
            #pragma unroll
            for (int q = 0; q < 4; q++){ yn[j][q] = y[j][q]; x[j][q] = y[j][q]; }
        }
    }

    // ldmatrix base addresses: thread lane -> row (lane&7), matrix (lane>>3)
    const uint32_t lm1 = smem_u32(W1s) + ((uint32_t)((lane & 7)*WSTRIDE + (lane >> 3)*8)) * 2u;
    const uint32_t lm2 = smem_u32(W2s) + ((uint32_t)((lane & 7)*WSTRIDE + (lane >> 3)*8)) * 2u;

    // ---- RK4 ODE: state stays in fragments; weights via ldmatrix ----
    const float h = 0.25f;
    float tcur = 0.f;
    #pragma unroll 1
    for (int step = 0; step < 4; step++){
        #pragma unroll 1
        for (int st = 0; st < 4; st++){
            const float tval = tcur + ((st == 0) ? 0.f : ((st == 3) ? h : 0.5f*h));

            // A1 fragments from x (cols 0..49 state, 50=t, 51=1, 52..63=0)
            uint32_t A[4][4];
            #pragma unroll
            for (int kk = 0; kk < 3; kk++){
                A[kk][0] = f2bf2(x[2*kk][0],   x[2*kk][1]);
                A[kk][1] = f2bf2(x[2*kk][2],   x[2*kk][3]);
                A[kk][2] = f2bf2(x[2*kk+1][0], x[2*kk+1][1]);
                A[kk][3] = f2bf2(x[2*kk+1][2], x[2*kk+1][3]);
            }
            {
                float a0 = x[6][0], a1 = x[6][1], a2 = x[6][2], a3 = x[6][3];
                if (tq == 1){ a0 = tval; a1 = 1.f; a2 = tval; a3 = 1.f; }
                A[3][0] = f2bf2(a0, a1); A[3][1] = f2bf2(a2, a3);
                A[3][2] = 0u; A[3][3] = 0u;
            }

            // MMA1: d = relu(inp @ W1 + b1)
            float d[7][4];
            #pragma unroll
            for (int j = 0; j < 7; j++){
                d[j][0] = d[j][1] = d[j][2] = d[j][3] = 0.f;
                const uint32_t a0 = lm1 + (uint32_t)(j*8*WSTRIDE*2);
                uint32_t b0, b1, b2, b3;
                LDSM_X4(b0, b1, b2, b3, a0);
                mma16816(d[j], A[0], b0, b1);
                mma16816(d[j], A[1], b2, b3);
                LDSM_X4(b0, b1, b2, b3, a0 + 64u);
                mma16816(d[j], A[2], b0, b1);
                mma16816(d[j], A[3], b2, b3);
            }
            #pragma unroll
            for (int j = 0; j < 7; j++){
                #pragma unroll
                for (int q = 0; q < 4; q++) d[j][q] = fmaxf(d[j][q], 0.f);
            }
            if (tq == 1){ d[6][0] = 1.f; d[6][2] = 1.f; }   // bias col 50 for MMA2

            // A2 fragments from d
            uint32_t A2r[4][4];
            #pragma unroll
            for (int kk = 0; kk < 3; kk++){
                A2r[kk][0] = f2bf2(d[2*kk][0],   d[2*kk][1]);
                A2r[kk][1] = f2bf2(d[2*kk][2],   d[2*kk][3]);
                A2r[kk][2] = f2bf2(d[2*kk+1][0], d[2*kk+1][1]);
                A2r[kk][3] = f2bf2(d[2*kk+1][2], d[2*kk+1][3]);
            }
            A2r[3][0] = f2bf2(d[6][0], d[6][1]);
            A2r[3][1] = f2bf2(d[6][2], d[6][3]);
            A2r[3][2] = 0u; A2r[3][3] = 0u;

            // MMA2: kv = z @ W2 + b2
            float kv[7][4];
            #pragma unroll
            for (int j = 0; j < 7; j++){
                kv[j][0] = kv[j][1] = kv[j][2] = kv[j][3] = 0.f;
                const uint32_t a0 = lm2 + (uint32_t)(j*8*WSTRIDE*2);
                uint32_t b0, b1, b2, b3;
                LDSM_X4(b0, b1, b2, b3, a0);
                mma16816(kv[j], A2r[0], b0, b1);
                mma16816(kv[j], A2r[1], b2, b3);
                LDSM_X4(b0, b1, b2, b3, a0 + 64u);
                mma16816(kv[j], A2r[2], b0, b1);
                mma16816(kv[j], A2r[3], b2, b3);
            }

            // RK4 combine (fp32)
            const float wc = (st == 0 || st == 3) ? h*(1.f/6.f) : h*(1.f/3.f);
            #pragma unroll
            for (int j = 0; j < 7; j++){
                #pragma unroll
                for (int q = 0; q < 4; q++) yn[j][q] = fmaf(wc, kv[j][q], yn[j][q]);
            }
            if (st < 3){
                const float ain = (st == 2) ? h : 0.5f*h;
                #pragma unroll
                for (int j = 0; j < 7; j++){
                    #pragma unroll
                    for (int q = 0; q < 4; q++) x[j][q] = fmaf(ain, kv[j][q], y[j][q]);
                }
            } else {
                #pragma unroll
                for (int j = 0; j < 7; j++){
                    #pragma unroll
                    for (int q = 0; q < 4; q++){ y[j][q] = yn[j][q]; x[j][q] = yn[j][q]; }
                }
                tcur += h;
            }
        }
    }

    // ---- write final state fragments back to stage ----
    {
        float* s0 = stg + (w*16 + gq)*STG_STRIDE + 2*tq;
        float* s1 = s0 + 8*STG_STRIDE;
        #pragma unroll
        for (int j = 0; j < 7; j++){
            s0[8*j] = yn[j][0];  s0[8*j + 1] = yn[j][1];
            s1[8*j] = yn[j][2];  s1[8*j + 1] = yn[j][3];
        }
    }
    __syncthreads();

    // ---- decoder (fp32 exact) ----
    if (valid){
        const float* sr = stg + tid*STG_STRIDE;
        float yT[50];
        #pragma unroll
        for (int k = 0; k < 50; k++) yT[k] = sr[k];

        float nl2[16];
        #pragma unroll
        for (int j = 0; j < 16; j++){
            float a = F[FNOB+j];
            #pragma unroll
            for (int k = 0; k < 50; k++) a = fmaf(yT[k], F[FNOW + k*16 + j], a);
            nl2[j] = a;
        }
        float d1[16];
        #pragma unroll
        for (int j = 0; j < 16; j++){
            float a = F[FDB1+j];
            #pragma unroll
            for (int k = 0; k < 16; k++) a = fmaf(nl2[k], F[FDW1 + k*16 + j], a);
            d1[j] = swishf(a);
        }
        float d2[16];
        #pragma unroll
        for (int j = 0; j < 16; j++){
            float a = F[FDB2+j];
            #pragma unroll
            for (int k = 0; k < 16; k++) a = fmaf(d1[k], F[FDW2 + k*16 + j], a);
            d2[j] = swishf(a);
        }
        float acc_p = F[FDB3];
        #pragma unroll
        for (int k = 0; k < 16; k++) acc_p = fmaf(d2[k], F[FDW3 + k], acc_p);

        const float vel = fmaf(acc_p, 0.01f, nd4);
        const float pos = fmaf(vel,   0.01f, nd0);
        out_nodes[i*6 + 0] = pos;
        out_nodes[i*6 + 1] = nd2;
        out_nodes[i*6 + 2] = nd3;
        out_nodes[i*6 + 3] = nd4;
        out_nodes[i*6 + 4] = vel;
        out_nodes[i*6 + 5] = acc_p;
        g_pos_buf[i] = pos;
    }
}

__global__ void gnode_edge_kernel(float* __restrict__ out_edges,
                                  const float* __restrict__ g,
                                  float* __restrict__ out_g, int e_cnt)
{
    int e = blockIdx.x * blockDim.x + threadIdx.x;
    if (e < e_cnt) out_edges[e] = g_pos_buf[e+1] - g_pos_buf[e];
    if (e == 0){ out_g[0] = g[0] + 1.f; out_g[1] = g[1]; }
}

extern "C" void kernel_launch(void* const* d_in, const int* in_sizes, int n_in,
                              void* d_out, int out_size)
{
    const float* nodes      = (const float*)d_in[0];
    const float* edges      = (const float*)d_in[1];
    const float* g          = (const float*)d_in[2];
    const float* enc_n_w1   = (const float*)d_in[3];
    const float* enc_n_b1   = (const float*)d_in[4];
    const float* enc_n_w2   = (const float*)d_in[5];
    const float* enc_n_b2   = (const float*)d_in[6];
    const float* enc_e_w1   = (const float*)d_in[7];
    const float* enc_e_b1   = (const float*)d_in[8];
    const float* enc_e_w2   = (const float*)d_in[9];
    const float* enc_e_b2   = (const float*)d_in[10];
    const float* ode_w1     = (const float*)d_in[11];
    const float* ode_b1     = (const float*)d_in[12];
    const float* ode_w2     = (const float*)d_in[13];
    const float* ode_b2     = (const float*)d_in[14];
    const float* node_out_w = (const float*)d_in[15];
    const float* node_out_b = (const float*)d_in[16];
    const float* dec_n_w1   = (const float*)d_in[17];
    const float* dec_n_b1   = (const float*)d_in[18];
    const float* dec_n_w2   = (const float*)d_in[19];
    const float* dec_n_b2   = (const float*)d_in[20];
    const float* dec_n_w3   = (const float*)d_in[21];
    const float* dec_n_b3   = (const float*)d_in[22];

    const int n = in_sizes[0] / 5;
    const int e_cnt = n - 1;
    float* out = (float*)d_out;
    float* out_edges = out + (size_t)n * 6;
    float* out_g = out_edges + e_cnt;

    cudaFuncSetAttribute(gnode_main_kernel,
                         cudaFuncAttributeMaxDynamicSharedMemorySize, DYN_BYTES);

    gnode_main_kernel<<<(n + NPB - 1) / NPB, TBS, DYN_BYTES>>>(
        nodes, edges, g,
        enc_n_w1, enc_n_b1, enc_n_w2, enc_n_b2,
        enc_e_w1, enc_e_b1, enc_e_w2, enc_e_b2,
        ode_w1, ode_b1, ode_w2, ode_b2,
        node_out_w, node_out_b,
        dec_n_w1, dec_n_b1, dec_n_w2, dec_n_b2, dec_n_w3, dec_n_b3,
        out, n);

    gnode_edge_kernel<<<(e_cnt + 255) / 256, 256>>>(out_edges, g, out_g, e_cnt);
}